// round 4
// baseline (speedup 1.0000x reference)
#include <cuda_runtime.h>

#define Bz 4
#define C_IN 32
#define NPIX 4096                        // 64*64 pooled pixels
#define NODES_PER_B (NPIX * C_IN)        // 131072
#define NODES_TOTAL (Bz * NODES_PER_B)   // 524288
#define ADJ_PER_B   ((long)NPIX * NPIX)  // 16777216 floats
#define EPSV 1e-6f

#define POOL_BLOCKS 64
#define TILE_FLOATS 32768                // 128KB tile = 8 adj rows
#define ROWS_PER_TILE 8
#define TILES_PER_B 512                  // ADJ_PER_B / TILE_FLOATS
#define ZERO_BLOCKS (Bz * TILES_PER_B)   // 2048

// patch certainty for pooled pixel p of batch b (x_var is tiny / L2-resident)
__device__ __forceinline__ float certainty(const float4* __restrict__ xv4, int b, int p)
{
    int R = p >> 6, C = p & 63;
    float s = 0.f;
    #pragma unroll
    for (int i = 0; i < 4; ++i) {
        float4 v = __ldg(&xv4[((b * 256 + (R * 4 + i)) << 6) + C]);
        s += v.x + v.y + v.z + v.w;
    }
    return 1.f - s * (1.f / 16.f);
}

__global__ __launch_bounds__(256) void fused_all(
    const float* __restrict__ x_feat,
    const float* __restrict__ x_var,
    float* __restrict__ out)
{
    int blk = blockIdx.x;
    int tid = threadIdx.x;

    if (blk < POOL_BLOCKS) {
        // ---- nodes: channel-summed 4x4 pool of x_feat, tiled 32x ----
        int g   = blk * 256 + tid;       // (b, t)
        int b   = g >> 12;
        int t   = g & 4095;
        int R   = t >> 6;
        int Cc  = t & 63;

        const float4* xf4 = (const float4*)x_feat;
        float s = 0.f;
        for (int c = 0; c < C_IN; ++c) {
            #pragma unroll
            for (int i = 0; i < 4; ++i) {
                // read-once: streaming load, don't pollute L2
                float4 v = __ldcs(&xf4[(((b * C_IN + c) * 256 + (R * 4 + i)) << 6) + Cc]);
                s += v.x + v.y + v.z + v.w;
            }
        }
        s *= (1.f / 16.f);

        float* nodes = out + (long)b * NODES_PER_B;
        #pragma unroll
        for (int j = 0; j < 32; ++j)
            __stcs(&nodes[j * NPIX + t], s);   // coalesced across t
        return;
    }

    // ---- adjacency tile: one 128KB tile (8 rows) per block ----
    int tile = blk - POOL_BLOCKS;        // 0..2047
    int b    = tile >> 9;                // batch
    int f0   = (tile & 511) << 3;        // first adj row of this tile

    float* adjb  = out + NODES_TOTAL + (long)b * ADJ_PER_B;
    float4* dst4 = (float4*)(adjb + (long)f0 * NPIX) + tid;

    // Phase a: stream 128KB of zeros; 32 unrolled streaming STG.128 off one base.
    const float4 z = make_float4(0.f, 0.f, 0.f, 0.f);
    #pragma unroll
    for (int k = 0; k < 32; ++k)
        __stcs(&dst4[k * 256], z);

    __syncthreads();   // orders the zeros before the patch stores below

    // Phase b: patch at most 32 candidate edges (8 rows x 4 neighbors).
    if (tid < 32) {
        int f   = f0 + (tid >> 2);
        int sel = tid & 3;
        int t; bool valid;
        if      (sel == 0) { t = f - 64; valid = (f >= 64);        }
        else if (sel == 1) { t = f + 64; valid = (f < NPIX - 64);  }
        else if (sel == 2) { t = f - 1;  valid = ((f & 63) != 0);  }
        else               { t = f + 1;  valid = ((f & 63) != 63); }
        if (valid) {
            const float4* xv4 = (const float4*)x_var;
            float w = certainty(xv4, b, f) - certainty(xv4, b, t);
            if (w > EPSV)
                adjb[(long)f * NPIX + t] = w;
        }
    }
}

extern "C" void kernel_launch(void* const* d_in, const int* in_sizes, int n_in,
                              void* d_out, int out_size)
{
    const float* x_feat = (const float*)d_in[0];
    const float* x_var  = (const float*)d_in[1];
    float* out = (float*)d_out;

    fused_all<<<POOL_BLOCKS + ZERO_BLOCKS, 256>>>(x_feat, x_var, out);
}